// round 15
// baseline (speedup 1.0000x reference)
#include <cuda_runtime.h>

#define BB 4
#define CC 256
#define HH 256
#define WW 256
#define RR 64
#define HL 64
#define WL 64
#define LRN (HL*WL)      // 4096
#define PLN (HH*WW)      // 65536

// Scratch (no allocation allowed -> device globals).
__device__ float g_fgp[2][BB*RR*LRN];   // 2 channel-group partials of fg
__device__ float g_ftp[2][BB*RR*LRN];   // 2 channel-group partials of ft
__device__ float g_a [BB*RR*LRN];
__device__ float g_bv[BB*RR*LRN];
__device__ float g_A [BB*CC*LRN];
__device__ float g_B [BB*CC*LRN];

typedef unsigned long long u64;

__device__ __forceinline__ u64 pack2(float lo, float hi) {
    u64 r; asm("mov.b64 %0, {%1, %2};" : "=l"(r) : "f"(lo), "f"(hi)); return r;
}
__device__ __forceinline__ void fma2(u64& d, u64 a, u64 b) {
    asm("fma.rn.f32x2 %0, %1, %2, %0;" : "+l"(d) : "l"(a), "l"(b));
}
__device__ __forceinline__ float2 unpk(u64 v) {
    float2 f; asm("mov.b64 {%0, %1}, %2;" : "=f"(f.x), "=f"(f.y) : "l"(v)); return f;
}

// K12 (fused): bilinear downsample 256->64 + partial C->R projection over a
// 128-channel group. Software-pipelined register prefetch. (EXACT R12 proven:
// part of the 247.9us best run.) grid (64,2,2), 256 threads, 40KB smem.
__global__ __launch_bounds__(256) void k_ds_proj(const float* __restrict__ enc,
                                                 const float* __restrict__ dec,
                                                 const float* __restrict__ wrg,
                                                 const float* __restrict__ wrt) {
    __shared__ float w_sm[128*RR];       // 32KB: [c_local][r]
    __shared__ float ds_sm[2][4*256];    // 2 x 4KB: [c_chunk_local][px_local]
    int cg = blockIdx.y;
    const float* in  = (blockIdx.z == 0) ? enc  : dec;
    const float* wt  = (blockIdx.z == 0) ? wrg  : wrt;   // [r][c] row-major
    float*       out = (blockIdx.z == 0) ? &g_fgp[cg][0] : &g_ftp[cg][0];
    int t = threadIdx.x;
    // Transposing fill: w_sm[c*64 + r] = wt[r*CC + cg*128 + c].
    for (int i = t; i < 128*RR; i += 256) {
        int c = i >> 6, r = i & 63;
        w_sm[i] = wt[r*CC + cg*128 + c];
    }

    int q = blockIdx.x * 256 + t;           // this thread's staging pixel
    int b = q >> 12, rest = q & 4095;
    int x = rest & 63, y = rest >> 6;
    const float* base = in + (size_t)b * CC * PLN + (size_t)cg * 128 * PLN
                           + (size_t)(4*y + 1) * WW + 4*x;

    int rg = t & 3, pg = t >> 2;            // GEMM role: 16 r's, 4 px's

    u64 acc[4][8];
    #pragma unroll
    for (int p = 0; p < 4; p++)
        #pragma unroll
        for (int j = 0; j < 8; j++) acc[p][j] = 0ull;

    // Prefetch chunk 0 into registers.
    float4 pre[4][2];
    #pragma unroll
    for (int cl = 0; cl < 4; cl++) {
        const float* p = base + (size_t)cl * PLN;
        pre[cl][0] = *(const float4*)p;
        pre[cl][1] = *(const float4*)(p + WW);
    }

    for (int ch = 0; ch < 32; ch++) {       // 32 chunks of 4 channels
        int buf = ch & 1;
        #pragma unroll
        for (int cl = 0; cl < 4; cl++)
            ds_sm[buf][cl*256 + t] =
                0.25f * ((pre[cl][0].y + pre[cl][0].z) + (pre[cl][1].y + pre[cl][1].z));
        __syncthreads();   // also orders w_sm fill before first gemm (ch=0)
        if (ch < 31) {
            #pragma unroll
            for (int cl = 0; cl < 4; cl++) {
                const float* p = base + (size_t)((ch + 1)*4 + cl) * PLN;
                pre[cl][0] = *(const float4*)p;
                pre[cl][1] = *(const float4*)(p + WW);
            }
        }
        #pragma unroll
        for (int cl = 0; cl < 4; cl++) {
            int c = ch*4 + cl;
            float4 d = *(const float4*)(ds_sm[buf] + cl*256 + pg*4);
            u64 d2[4];
            d2[0] = pack2(d.x, d.x); d2[1] = pack2(d.y, d.y);
            d2[2] = pack2(d.z, d.z); d2[3] = pack2(d.w, d.w);
            const ulonglong2* wp = (const ulonglong2*)(w_sm + c*RR + rg*16);
            #pragma unroll
            for (int jj = 0; jj < 4; jj++) {
                ulonglong2 wv = wp[jj];
                #pragma unroll
                for (int p = 0; p < 4; p++) {
                    fma2(acc[p][2*jj    ], wv.x, d2[p]);
                    fma2(acc[p][2*jj + 1], wv.y, d2[p]);
                }
            }
        }
    }
    int rest0 = (blockIdx.x * 256 + pg*4) & 4095;
    float* pout = out + (size_t)b * RR * LRN + rest0 + (size_t)(rg*16) * LRN;
    #pragma unroll
    for (int k = 0; k < 8; k++) {
        float2 u0 = unpk(acc[0][k]), u1 = unpk(acc[1][k]);
        float2 u2 = unpk(acc[2][k]), u3 = unpk(acc[3][k]);
        *(float4*)(pout + (size_t)(2*k    ) * LRN) = make_float4(u0.x, u1.x, u2.x, u3.x);
        *(float4*)(pout + (size_t)(2*k + 1) * LRN) = make_float4(u0.y, u1.y, u2.y, u3.y);
    }
}

// K3a: sum 2 channel-group partials, 3x3 zero-padded box mean (/9) + a,b.
// Split into y-halves: grid 512 = (b*RR + r) * 2 halves, 34-row halo tiles.
__global__ __launch_bounds__(256) void k_guided(const float* __restrict__ eps_p) {
    __shared__ float gs[34*64], ts[34*64];
    int pl   = blockIdx.x >> 1;     // b*RR + r
    int half = blockIdx.x & 1;
    int y0   = half * 32;
    size_t off = (size_t)pl * LRN;
    int t = threadIdx.x;
    for (int i = t; i < 34*64; i += 256) {
        int ry = (i >> 6) + y0 - 1;
        float gv = 0.f, tv = 0.f;
        if (ry >= 0 && ry < 64) {
            int idx = ry*64 + (i & 63);
            gv = g_fgp[0][off+idx] + g_fgp[1][off+idx];
            tv = g_ftp[0][off+idx] + g_ftp[1][off+idx];
        }
        gs[i] = gv; ts[i] = tv;
    }
    __syncthreads();
    float eps = *eps_p;
    const float inv9 = 1.0f / 9.0f;
    for (int i = t; i < 32*64; i += 256) {
        int yl = (i >> 6) + 1;      // smem row (halo offset)
        int x  = i & 63;
        float sg = 0.f, st = 0.f, sgg = 0.f, sgt = 0.f;
        #pragma unroll
        for (int dy = -1; dy <= 1; dy++) {
            const float* gr = gs + (yl+dy)*64;
            const float* tr = ts + (yl+dy)*64;
            #pragma unroll
            for (int dx = -1; dx <= 1; dx++) {
                int xx = x + dx;
                if (xx < 0 || xx > 63) continue;
                float g = gr[xx], v = tr[xx];
                sg += g; st += v; sgg += g*g; sgt += g*v;
            }
        }
        float mg  = sg  * inv9, mt = st * inv9;
        float var = sgg * inv9 - mg*mg;
        float cov = sgt * inv9 - mg*mt;
        float a  = cov / (var + eps);
        float bv = mt - a * mg;
        int oidx = (y0 + (i >> 6))*64 + x;
        g_a [off + oidx] = a;
        g_bv[off + oidx] = bv;
    }
}

// K3b: R=64 -> C=256 projection at low-res, smem-staged GEMM (under test).
// Block loads a-tile [64r][128px] (32KB) + w-tile [64r][64o] (16KB) once;
// inner loop is all-smem. Per thread: px2 x o16.
// grid: (128 px-blocks, 4 o-blocks, 2 tensors), 256 threads.
__global__ __launch_bounds__(256) void k_proj_rc(const float* __restrict__ wua,
                                                 const float* __restrict__ wub) {
    __shared__ float a_sm[RR*128];   // 32KB: [r][px_local]
    __shared__ float w_sm[RR*64];    // 16KB: [r][o_local]
    const float* wt  = (blockIdx.z == 0) ? wua  : wub;   // [o][r] row-major
    const float* src = (blockIdx.z == 0) ? g_a  : g_bv;
    float*       dst = (blockIdx.z == 0) ? g_A  : g_B;
    int o0 = blockIdx.y * 64;
    int t = threadIdx.x;
    int q0 = blockIdx.x * 128;          // 128 px per block, within one b
    int b = q0 >> 12, rest0 = q0 & 4095;
    const float* ps = src + (size_t)b * RR * LRN + rest0;
    // a-tile: 2048 float4, coalesced per row.
    for (int i = t; i < RR*32; i += 256) {
        int r = i >> 5, j = i & 31;
        *(float4*)(a_sm + r*128 + j*4) = *(const float4*)(ps + (size_t)r * LRN + j*4);
    }
    // w-tile transposing fill: w_sm[r*64 + j] = wt[(o0+j)*RR + r].
    for (int i = t; i < RR*64; i += 256) {
        int r = i >> 6, j = i & 63;
        w_sm[r*64 + j] = wt[(o0 + j)*RR + r];
    }
    __syncthreads();
    int tx = t & 63, ty = t >> 6;       // px-group (2 px), o-group (16 o)
    int px = tx*2, ob = ty*16;
    u64 acc0[8], acc1[8];
    #pragma unroll
    for (int j = 0; j < 8; j++) { acc0[j]=0ull; acc1[j]=0ull; }
    #pragma unroll 8
    for (int r = 0; r < RR; r++) {
        float2 v = *(const float2*)(a_sm + r*128 + px);
        u64 v0 = pack2(v.x, v.x), v1 = pack2(v.y, v.y);
        const ulonglong2* wp = (const ulonglong2*)(w_sm + r*64 + ob);
        #pragma unroll
        for (int j = 0; j < 4; j++) {
            ulonglong2 w = wp[j];
            fma2(acc0[2*j  ], w.x, v0); fma2(acc1[2*j  ], w.x, v1);
            fma2(acc0[2*j+1], w.y, v0); fma2(acc1[2*j+1], w.y, v1);
        }
    }
    float* od = dst + (size_t)b * CC * LRN + rest0 + px;
    #pragma unroll
    for (int j = 0; j < 8; j++) {
        float2 u0 = unpk(acc0[j]), u1 = unpk(acc1[j]);
        *(float2*)(od + (size_t)(o0 + ob + 2*j    ) * LRN) = make_float2(u0.x, u1.x);
        *(float2*)(od + (size_t)(o0 + ob + 2*j + 1) * LRN) = make_float2(u0.y, u1.y);
    }
}

// Per-y bilinear interp of A,B rows from smem (rows local to rbase).
__device__ __forceinline__ void interp_ab(const float* As, const float* Bs,
                                          int y, int rbase, int xg, int cm, int cp,
                                          float4& Av, float4& Bv) {
    float sy = fmaxf((float)y * 0.25f - 0.375f, 0.0f);
    int y0 = (int)sy;
    float wy = sy - (float)y0;
    int y1 = min(y0 + 1, 63);
    const float* rA0 = As + (y0 - rbase)*64; const float* rA1 = As + (y1 - rbase)*64;
    const float* rB0 = Bs + (y0 - rbase)*64; const float* rB1 = Bs + (y1 - rbase)*64;
    float am = rA0[cm] + wy * (rA1[cm] - rA0[cm]);
    float ac = rA0[xg] + wy * (rA1[xg] - rA0[xg]);
    float ap = rA0[cp] + wy * (rA1[cp] - rA0[cp]);
    float bm = rB0[cm] + wy * (rB1[cm] - rB0[cm]);
    float bc = rB0[xg] + wy * (rB1[xg] - rB0[xg]);
    float bp = rB0[cp] + wy * (rB1[cp] - rB0[cp]);
    if (xg == 0) { Av.x = ac; Av.y = ac; Bv.x = bc; Bv.y = bc; }   // src clamp, w=0
    else {
        Av.x = am + 0.625f * (ac - am);
        Av.y = am + 0.875f * (ac - am);
        Bv.x = bm + 0.625f * (bc - bm);
        Bv.y = bm + 0.875f * (bc - bm);
    }
    Av.z = ac + 0.125f * (ap - ac); Av.w = ac + 0.375f * (ap - ac);
    Bv.z = bc + 0.125f * (bp - bc); Bv.w = bc + 0.375f * (bp - bc);
}

// K4: fused bilinear 64->256 upsample of A,B + out = F_dec + A*F_enc + B.
// (Proven R12: 132.7us @ 77% DRAM — at its bandwidth ceiling. Control kernel.)
__global__ __launch_bounds__(256) void k_fuse(const float* __restrict__ enc,
                                              const float* __restrict__ dec,
                                              float* __restrict__ out) {
    __shared__ float As[33*64], Bs[33*64];
    int plane = blockIdx.x;
    int half  = blockIdx.y;
    int rbase = half * 31;          // lowres rows rbase..rbase+32 cover this half
    const float* Ap = g_A + (size_t)plane * LRN + rbase*64;
    const float* Bp = g_B + (size_t)plane * LRN + rbase*64;
    int t = threadIdx.x;
    for (int i = t; i < 33*64; i += 256) { As[i] = Ap[i]; Bs[i] = Bp[i]; }
    __syncthreads();
    const float* ep = enc + (size_t)plane * PLN;
    const float* dp = dec + (size_t)plane * PLN;
    float*       op = out + (size_t)plane * PLN;
    int xg = t & 63, ys = t >> 6;
    int cm = max(xg - 1, 0), cp = min(xg + 1, 63);
    int ybase = half*128 + ys;
    #pragma unroll
    for (int yy = 0; yy < 32; yy += 4) {
        int yv[4]; size_t offv[4];
        float4 ev[4], dv[4];
        #pragma unroll
        for (int u = 0; u < 4; u++) {
            yv[u] = ybase + (yy + u)*4;
            offv[u] = (size_t)yv[u] * WW + xg * 4;
        }
        #pragma unroll
        for (int u = 0; u < 4; u++) ev[u] = *(const float4*)(ep + offv[u]);
        #pragma unroll
        for (int u = 0; u < 4; u++) dv[u] = *(const float4*)(dp + offv[u]);
        #pragma unroll
        for (int u = 0; u < 4; u++) {
            float4 Av, Bv;
            interp_ab(As, Bs, yv[u], rbase, xg, cm, cp, Av, Bv);
            float4 o;
            o.x = dv[u].x + Av.x * ev[u].x + Bv.x;
            o.y = dv[u].y + Av.y * ev[u].y + Bv.y;
            o.z = dv[u].z + Av.z * ev[u].z + Bv.z;
            o.w = dv[u].w + Av.w * ev[u].w + Bv.w;
            *(float4*)(op + offv[u]) = o;
        }
    }
}

extern "C" void kernel_launch(void* const* d_in, const int* in_sizes, int n_in,
                              void* d_out, int out_size) {
    const float* F_enc = (const float*)d_in[0];
    const float* F_dec = (const float*)d_in[1];
    const float* w_rg  = (const float*)d_in[2];
    const float* w_rt  = (const float*)d_in[3];
    const float* w_ua  = (const float*)d_in[4];
    const float* w_ub  = (const float*)d_in[5];
    const float* eps   = (const float*)d_in[6];
    float* out = (float*)d_out;

    k_ds_proj<<<dim3(64, 2, 2), 256>>>(F_enc, F_dec, w_rg, w_rt);  // launch 1 (R12 proven)
    k_guided<<<BB*RR*2, 256>>>(eps);                                // launch 2 (R12 proven)
    k_proj_rc<<<dim3(128, 4, 2), 256>>>(w_ua, w_ub);                // launch 3 (smem, under test)
    k_fuse<<<dim3(BB*CC, 2), 256>>>(F_enc, F_dec, out);             // launch 4 -> ncu control
}

// round 16
// speedup vs baseline: 1.0404x; 1.0404x over previous
#include <cuda_runtime.h>

#define BB 4
#define CC 256
#define HH 256
#define WW 256
#define RR 64
#define HL 64
#define WL 64
#define LRN (HL*WL)      // 4096
#define PLN (HH*WW)      // 65536

// Scratch (no allocation allowed -> device globals).
__device__ float g_fgp[2][BB*RR*LRN];   // 2 channel-group partials of fg
__device__ float g_ftp[2][BB*RR*LRN];   // 2 channel-group partials of ft
__device__ float g_a [BB*RR*LRN];
__device__ float g_bv[BB*RR*LRN];
__device__ float g_A [BB*CC*LRN];
__device__ float g_B [BB*CC*LRN];

typedef unsigned long long u64;

__device__ __forceinline__ u64 pack2(float lo, float hi) {
    u64 r; asm("mov.b64 %0, {%1, %2};" : "=l"(r) : "f"(lo), "f"(hi)); return r;
}
__device__ __forceinline__ void fma2(u64& d, u64 a, u64 b) {
    asm("fma.rn.f32x2 %0, %1, %2, %0;" : "+l"(d) : "l"(a), "l"(b));
}
__device__ __forceinline__ float2 unpk(u64 v) {
    float2 f; asm("mov.b64 {%0, %1}, %2;" : "=f"(f.x), "=f"(f.y) : "l"(v)); return f;
}

// K12 (fused): bilinear downsample 256->64 + partial C->R projection over a
// 128-channel group. BARRIER-FREE main loop: the ds exchange is intra-quad
// (thread t needs pixels (t&~3)+k, k=0..3 -> its own quad's lanes), so
// smem STS/sync/LDS is replaced by 4 __shfl_sync per channel. Register
// prefetch distance 1; warps fully independent after the weight fill.
// grid: (64 px-blocks, 2 c-groups, 2 tensors), 256 threads, 32KB smem.
__global__ __launch_bounds__(256) void k_ds_proj(const float* __restrict__ enc,
                                                 const float* __restrict__ dec,
                                                 const float* __restrict__ wrg,
                                                 const float* __restrict__ wrt) {
    __shared__ float w_sm[128*RR];       // 32KB: [c_local][r]
    int cg = blockIdx.y;
    const float* in  = (blockIdx.z == 0) ? enc  : dec;
    const float* wt  = (blockIdx.z == 0) ? wrg  : wrt;   // [r][c] row-major
    float*       out = (blockIdx.z == 0) ? &g_fgp[cg][0] : &g_ftp[cg][0];
    int t = threadIdx.x;
    // Transposing fill: w_sm[c*64 + r] = wt[r*CC + cg*128 + c].
    for (int i = t; i < 128*RR; i += 256) {
        int c = i >> 6, r = i & 63;
        w_sm[i] = wt[r*CC + cg*128 + c];
    }
    __syncthreads();   // the ONLY block barrier

    int q = blockIdx.x * 256 + t;           // this thread's staging pixel
    int b = q >> 12, rest = q & 4095;
    int x = rest & 63, y = rest >> 6;
    const float* base = in + (size_t)b * CC * PLN + (size_t)cg * 128 * PLN
                           + (size_t)(4*y + 1) * WW + 4*x;

    int rg = t & 3, pg = t >> 2;            // GEMM role: 16 r's, 4 px's
    int qb = t & 28;                        // quad base lane (t&31 & ~3)

    u64 acc[4][8];
    #pragma unroll
    for (int p = 0; p < 4; p++)
        #pragma unroll
        for (int j = 0; j < 8; j++) acc[p][j] = 0ull;

    // Prefetch chunk 0 into registers.
    float4 pre[4][2];
    #pragma unroll
    for (int cl = 0; cl < 4; cl++) {
        const float* p = base + (size_t)cl * PLN;
        pre[cl][0] = *(const float4*)p;
        pre[cl][1] = *(const float4*)(p + WW);
    }

    for (int ch = 0; ch < 32; ch++) {       // 32 chunks of 4 channels
        float ds[4];
        #pragma unroll
        for (int cl = 0; cl < 4; cl++)
            ds[cl] = 0.25f * ((pre[cl][0].y + pre[cl][0].z) + (pre[cl][1].y + pre[cl][1].z));
        // Issue next chunk's LDGs now — consumed only next iteration, so their
        // latency is covered by this chunk's 128 fma2 (no barrier in between).
        if (ch < 31) {
            #pragma unroll
            for (int cl = 0; cl < 4; cl++) {
                const float* p = base + (size_t)((ch + 1)*4 + cl) * PLN;
                pre[cl][0] = *(const float4*)p;
                pre[cl][1] = *(const float4*)(p + WW);
            }
        }
        #pragma unroll
        for (int cl = 0; cl < 4; cl++) {
            int c = ch*4 + cl;
            u64 d2[4];
            #pragma unroll
            for (int k = 0; k < 4; k++) {
                float v = __shfl_sync(0xffffffffu, ds[cl], qb + k);
                d2[k] = pack2(v, v);
            }
            const ulonglong2* wp = (const ulonglong2*)(w_sm + c*RR + rg*16);
            #pragma unroll
            for (int jj = 0; jj < 4; jj++) {
                ulonglong2 wv = wp[jj];
                #pragma unroll
                for (int p = 0; p < 4; p++) {
                    fma2(acc[p][2*jj    ], wv.x, d2[p]);
                    fma2(acc[p][2*jj + 1], wv.y, d2[p]);
                }
            }
        }
    }
    int rest0 = (blockIdx.x * 256 + pg*4) & 4095;
    float* pout = out + (size_t)b * RR * LRN + rest0 + (size_t)(rg*16) * LRN;
    #pragma unroll
    for (int k = 0; k < 8; k++) {
        float2 u0 = unpk(acc[0][k]), u1 = unpk(acc[1][k]);
        float2 u2 = unpk(acc[2][k]), u3 = unpk(acc[3][k]);
        *(float4*)(pout + (size_t)(2*k    ) * LRN) = make_float4(u0.x, u1.x, u2.x, u3.x);
        *(float4*)(pout + (size_t)(2*k + 1) * LRN) = make_float4(u0.y, u1.y, u2.y, u3.y);
    }
}

// K3a: sum 2 channel-group partials, 3x3 zero-padded box mean (/9) + a,b.
// Split into y-halves: grid 512 = (b*RR + r) * 2 halves, 34-row halo tiles.
__global__ __launch_bounds__(256) void k_guided(const float* __restrict__ eps_p) {
    __shared__ float gs[34*64], ts[34*64];
    int pl   = blockIdx.x >> 1;     // b*RR + r
    int half = blockIdx.x & 1;
    int y0   = half * 32;
    size_t off = (size_t)pl * LRN;
    int t = threadIdx.x;
    for (int i = t; i < 34*64; i += 256) {
        int ry = (i >> 6) + y0 - 1;
        float gv = 0.f, tv = 0.f;
        if (ry >= 0 && ry < 64) {
            int idx = ry*64 + (i & 63);
            gv = g_fgp[0][off+idx] + g_fgp[1][off+idx];
            tv = g_ftp[0][off+idx] + g_ftp[1][off+idx];
        }
        gs[i] = gv; ts[i] = tv;
    }
    __syncthreads();
    float eps = *eps_p;
    const float inv9 = 1.0f / 9.0f;
    for (int i = t; i < 32*64; i += 256) {
        int yl = (i >> 6) + 1;      // smem row (halo offset)
        int x  = i & 63;
        float sg = 0.f, st = 0.f, sgg = 0.f, sgt = 0.f;
        #pragma unroll
        for (int dy = -1; dy <= 1; dy++) {
            const float* gr = gs + (yl+dy)*64;
            const float* tr = ts + (yl+dy)*64;
            #pragma unroll
            for (int dx = -1; dx <= 1; dx++) {
                int xx = x + dx;
                if (xx < 0 || xx > 63) continue;
                float g = gr[xx], v = tr[xx];
                sg += g; st += v; sgg += g*g; sgt += g*v;
            }
        }
        float mg  = sg  * inv9, mt = st * inv9;
        float var = sgg * inv9 - mg*mg;
        float cov = sgt * inv9 - mg*mt;
        float a  = cov / (var + eps);
        float bv = mt - a * mg;
        int oidx = (y0 + (i >> 6))*64 + x;
        g_a [off + oidx] = a;
        g_bv[off + oidx] = bv;
    }
}

// K3b: R=64 -> C=256 projection at low-res. px-tile=2, o-tile=16,
// A/B split across blockIdx.z (EXACT R12 proven: 38.1us, part of 247.9 best).
__global__ __launch_bounds__(256) void k_proj_rc(const float* __restrict__ wua,
                                                 const float* __restrict__ wub) {
    __shared__ float w_sm[RR*16];
    const float* wt  = (blockIdx.z == 0) ? wua  : wub;   // [o][r] row-major
    const float* src = (blockIdx.z == 0) ? g_a  : g_bv;
    float*       dst = (blockIdx.z == 0) ? g_A  : g_B;
    int o0 = blockIdx.y * 16;
    int t = threadIdx.x;
    for (int i = t; i < RR*16; i += 256) {
        int r = i >> 4, j = i & 15;
        w_sm[i] = wt[(o0 + j)*RR + r];
    }
    __syncthreads();
    int q = (blockIdx.x * 256 + t) * 2;     // 2 consecutive pixels
    int b = q >> 12, rest = q & 4095;
    const float* ps = src + (size_t)b * RR * LRN + rest;
    u64 acc0[8], acc1[8];
    #pragma unroll
    for (int j = 0; j < 8; j++) { acc0[j]=0ull; acc1[j]=0ull; }
    #pragma unroll 4
    for (int r = 0; r < RR; r++) {
        float2 v = *(const float2*)(ps + (size_t)r * LRN);
        u64 v0 = pack2(v.x, v.x), v1 = pack2(v.y, v.y);
        const ulonglong2* wp = (const ulonglong2*)(w_sm + r*16);
        #pragma unroll
        for (int j = 0; j < 4; j++) {
            ulonglong2 w = wp[j];
            fma2(acc0[2*j  ], w.x, v0); fma2(acc1[2*j  ], w.x, v1);
            fma2(acc0[2*j+1], w.y, v0); fma2(acc1[2*j+1], w.y, v1);
        }
    }
    float* od = dst + (size_t)b * CC * LRN + rest;
    #pragma unroll
    for (int j = 0; j < 8; j++) {
        float2 u0 = unpk(acc0[j]), u1 = unpk(acc1[j]);
        *(float2*)(od + (size_t)(o0 + 2*j    ) * LRN) = make_float2(u0.x, u1.x);
        *(float2*)(od + (size_t)(o0 + 2*j + 1) * LRN) = make_float2(u0.y, u1.y);
    }
}

// Per-y bilinear interp of A,B rows from smem (rows local to rbase).
__device__ __forceinline__ void interp_ab(const float* As, const float* Bs,
                                          int y, int rbase, int xg, int cm, int cp,
                                          float4& Av, float4& Bv) {
    float sy = fmaxf((float)y * 0.25f - 0.375f, 0.0f);
    int y0 = (int)sy;
    float wy = sy - (float)y0;
    int y1 = min(y0 + 1, 63);
    const float* rA0 = As + (y0 - rbase)*64; const float* rA1 = As + (y1 - rbase)*64;
    const float* rB0 = Bs + (y0 - rbase)*64; const float* rB1 = Bs + (y1 - rbase)*64;
    float am = rA0[cm] + wy * (rA1[cm] - rA0[cm]);
    float ac = rA0[xg] + wy * (rA1[xg] - rA0[xg]);
    float ap = rA0[cp] + wy * (rA1[cp] - rA0[cp]);
    float bm = rB0[cm] + wy * (rB1[cm] - rB0[cm]);
    float bc = rB0[xg] + wy * (rB1[xg] - rB0[xg]);
    float bp = rB0[cp] + wy * (rB1[cp] - rB0[cp]);
    if (xg == 0) { Av.x = ac; Av.y = ac; Bv.x = bc; Bv.y = bc; }   // src clamp, w=0
    else {
        Av.x = am + 0.625f * (ac - am);
        Av.y = am + 0.875f * (ac - am);
        Bv.x = bm + 0.625f * (bc - bm);
        Bv.y = bm + 0.875f * (bc - bm);
    }
    Av.z = ac + 0.125f * (ap - ac); Av.w = ac + 0.375f * (ap - ac);
    Bv.z = bc + 0.125f * (bp - bc); Bv.w = bc + 0.375f * (bp - bc);
}

// K4: fused bilinear 64->256 upsample of A,B + out = F_dec + A*F_enc + B.
// (Proven R12: 132.7us @ 77% DRAM — at its bandwidth ceiling. Control kernel.)
__global__ __launch_bounds__(256) void k_fuse(const float* __restrict__ enc,
                                              const float* __restrict__ dec,
                                              float* __restrict__ out) {
    __shared__ float As[33*64], Bs[33*64];
    int plane = blockIdx.x;
    int half  = blockIdx.y;
    int rbase = half * 31;          // lowres rows rbase..rbase+32 cover this half
    const float* Ap = g_A + (size_t)plane * LRN + rbase*64;
    const float* Bp = g_B + (size_t)plane * LRN + rbase*64;
    int t = threadIdx.x;
    for (int i = t; i < 33*64; i += 256) { As[i] = Ap[i]; Bs[i] = Bp[i]; }
    __syncthreads();
    const float* ep = enc + (size_t)plane * PLN;
    const float* dp = dec + (size_t)plane * PLN;
    float*       op = out + (size_t)plane * PLN;
    int xg = t & 63, ys = t >> 6;
    int cm = max(xg - 1, 0), cp = min(xg + 1, 63);
    int ybase = half*128 + ys;
    #pragma unroll
    for (int yy = 0; yy < 32; yy += 4) {
        int yv[4]; size_t offv[4];
        float4 ev[4], dv[4];
        #pragma unroll
        for (int u = 0; u < 4; u++) {
            yv[u] = ybase + (yy + u)*4;
            offv[u] = (size_t)yv[u] * WW + xg * 4;
        }
        #pragma unroll
        for (int u = 0; u < 4; u++) ev[u] = *(const float4*)(ep + offv[u]);
        #pragma unroll
        for (int u = 0; u < 4; u++) dv[u] = *(const float4*)(dp + offv[u]);
        #pragma unroll
        for (int u = 0; u < 4; u++) {
            float4 Av, Bv;
            interp_ab(As, Bs, yv[u], rbase, xg, cm, cp, Av, Bv);
            float4 o;
            o.x = dv[u].x + Av.x * ev[u].x + Bv.x;
            o.y = dv[u].y + Av.y * ev[u].y + Bv.y;
            o.z = dv[u].z + Av.z * ev[u].z + Bv.z;
            o.w = dv[u].w + Av.w * ev[u].w + Bv.w;
            *(float4*)(op + offv[u]) = o;
        }
    }
}

extern "C" void kernel_launch(void* const* d_in, const int* in_sizes, int n_in,
                              void* d_out, int out_size) {
    const float* F_enc = (const float*)d_in[0];
    const float* F_dec = (const float*)d_in[1];
    const float* w_rg  = (const float*)d_in[2];
    const float* w_rt  = (const float*)d_in[3];
    const float* w_ua  = (const float*)d_in[4];
    const float* w_ub  = (const float*)d_in[5];
    const float* eps   = (const float*)d_in[6];
    float* out = (float*)d_out;

    k_ds_proj<<<dim3(64, 2, 2), 256>>>(F_enc, F_dec, w_rg, w_rt);  // launch 1 (shuffle, under test)
    k_guided<<<BB*RR*2, 256>>>(eps);                                // launch 2 (proven)
    k_proj_rc<<<dim3(32, 16, 2), 256>>>(w_ua, w_ub);                // launch 3 (R12 proven)
    k_fuse<<<dim3(BB*CC, 2), 256>>>(F_enc, F_dec, out);             // launch 4 -> ncu control
}

// round 17
// speedup vs baseline: 1.0430x; 1.0025x over previous
#include <cuda_runtime.h>

#define BB 4
#define CC 256
#define HH 256
#define WW 256
#define RR 64
#define HL 64
#define WL 64
#define LRN (HL*WL)      // 4096
#define PLN (HH*WW)      // 65536

// Scratch (no allocation allowed -> device globals).
__device__ float g_fgp[2][BB*RR*LRN];   // 2 channel-group partials of fg
__device__ float g_ftp[2][BB*RR*LRN];   // 2 channel-group partials of ft
__device__ float g_a [BB*RR*LRN];
__device__ float g_bv[BB*RR*LRN];
__device__ float g_A [BB*CC*LRN];
__device__ float g_B [BB*CC*LRN];

typedef unsigned long long u64;

__device__ __forceinline__ u64 pack2(float lo, float hi) {
    u64 r; asm("mov.b64 %0, {%1, %2};" : "=l"(r) : "f"(lo), "f"(hi)); return r;
}
__device__ __forceinline__ void fma2(u64& d, u64 a, u64 b) {
    asm("fma.rn.f32x2 %0, %1, %2, %0;" : "+l"(d) : "l"(a), "l"(b));
}
__device__ __forceinline__ float2 unpk(u64 v) {
    float2 f; asm("mov.b64 {%0, %1}, %2;" : "=f"(f.x), "=f"(f.y) : "l"(v)); return f;
}

// K12 (fused): bilinear downsample 256->64 + partial C->R projection over a
// 128-channel group. BARRIER-FREE main loop (proven R16): ds exchange is
// intra-quad via __shfl_sync; register prefetch distance 1.
// grid: (64 px-blocks, 2 c-groups, 2 tensors), 256 threads, 32KB smem.
__global__ __launch_bounds__(256) void k_ds_proj(const float* __restrict__ enc,
                                                 const float* __restrict__ dec,
                                                 const float* __restrict__ wrg,
                                                 const float* __restrict__ wrt) {
    __shared__ float w_sm[128*RR];       // 32KB: [c_local][r]
    int cg = blockIdx.y;
    const float* in  = (blockIdx.z == 0) ? enc  : dec;
    const float* wt  = (blockIdx.z == 0) ? wrg  : wrt;   // [r][c] row-major
    float*       out = (blockIdx.z == 0) ? &g_fgp[cg][0] : &g_ftp[cg][0];
    int t = threadIdx.x;
    // Transposing fill: w_sm[c*64 + r] = wt[r*CC + cg*128 + c].
    for (int i = t; i < 128*RR; i += 256) {
        int c = i >> 6, r = i & 63;
        w_sm[i] = wt[r*CC + cg*128 + c];
    }
    __syncthreads();   // the ONLY block barrier

    int q = blockIdx.x * 256 + t;           // this thread's staging pixel
    int b = q >> 12, rest = q & 4095;
    int x = rest & 63, y = rest >> 6;
    const float* base = in + (size_t)b * CC * PLN + (size_t)cg * 128 * PLN
                           + (size_t)(4*y + 1) * WW + 4*x;

    int rg = t & 3, pg = t >> 2;            // GEMM role: 16 r's, 4 px's
    int qb = t & 28;                        // quad base lane

    u64 acc[4][8];
    #pragma unroll
    for (int p = 0; p < 4; p++)
        #pragma unroll
        for (int j = 0; j < 8; j++) acc[p][j] = 0ull;

    // Prefetch chunk 0 into registers.
    float4 pre[4][2];
    #pragma unroll
    for (int cl = 0; cl < 4; cl++) {
        const float* p = base + (size_t)cl * PLN;
        pre[cl][0] = *(const float4*)p;
        pre[cl][1] = *(const float4*)(p + WW);
    }

    for (int ch = 0; ch < 32; ch++) {       // 32 chunks of 4 channels
        float ds[4];
        #pragma unroll
        for (int cl = 0; cl < 4; cl++)
            ds[cl] = 0.25f * ((pre[cl][0].y + pre[cl][0].z) + (pre[cl][1].y + pre[cl][1].z));
        if (ch < 31) {
            #pragma unroll
            for (int cl = 0; cl < 4; cl++) {
                const float* p = base + (size_t)((ch + 1)*4 + cl) * PLN;
                pre[cl][0] = *(const float4*)p;
                pre[cl][1] = *(const float4*)(p + WW);
            }
        }
        #pragma unroll
        for (int cl = 0; cl < 4; cl++) {
            int c = ch*4 + cl;
            u64 d2[4];
            #pragma unroll
            for (int k = 0; k < 4; k++) {
                float v = __shfl_sync(0xffffffffu, ds[cl], qb + k);
                d2[k] = pack2(v, v);
            }
            const ulonglong2* wp = (const ulonglong2*)(w_sm + c*RR + rg*16);
            #pragma unroll
            for (int jj = 0; jj < 4; jj++) {
                ulonglong2 wv = wp[jj];
                #pragma unroll
                for (int p = 0; p < 4; p++) {
                    fma2(acc[p][2*jj    ], wv.x, d2[p]);
                    fma2(acc[p][2*jj + 1], wv.y, d2[p]);
                }
            }
        }
    }
    int rest0 = (blockIdx.x * 256 + pg*4) & 4095;
    float* pout = out + (size_t)b * RR * LRN + rest0 + (size_t)(rg*16) * LRN;
    #pragma unroll
    for (int k = 0; k < 8; k++) {
        float2 u0 = unpk(acc[0][k]), u1 = unpk(acc[1][k]);
        float2 u2 = unpk(acc[2][k]), u3 = unpk(acc[3][k]);
        *(float4*)(pout + (size_t)(2*k    ) * LRN) = make_float4(u0.x, u1.x, u2.x, u3.x);
        *(float4*)(pout + (size_t)(2*k + 1) * LRN) = make_float4(u0.y, u1.y, u2.y, u3.y);
    }
}

// K3a: sum 2 channel-group partials, 3x3 zero-padded box mean (/9) + a,b.
// Split into y-halves: grid 512 = (b*RR + r) * 2 halves, 34-row halo tiles.
__global__ __launch_bounds__(256) void k_guided(const float* __restrict__ eps_p) {
    __shared__ float gs[34*64], ts[34*64];
    int pl   = blockIdx.x >> 1;     // b*RR + r
    int half = blockIdx.x & 1;
    int y0   = half * 32;
    size_t off = (size_t)pl * LRN;
    int t = threadIdx.x;
    for (int i = t; i < 34*64; i += 256) {
        int ry = (i >> 6) + y0 - 1;
        float gv = 0.f, tv = 0.f;
        if (ry >= 0 && ry < 64) {
            int idx = ry*64 + (i & 63);
            gv = g_fgp[0][off+idx] + g_fgp[1][off+idx];
            tv = g_ftp[0][off+idx] + g_ftp[1][off+idx];
        }
        gs[i] = gv; ts[i] = tv;
    }
    __syncthreads();
    float eps = *eps_p;
    const float inv9 = 1.0f / 9.0f;
    for (int i = t; i < 32*64; i += 256) {
        int yl = (i >> 6) + 1;      // smem row (halo offset)
        int x  = i & 63;
        float sg = 0.f, st = 0.f, sgg = 0.f, sgt = 0.f;
        #pragma unroll
        for (int dy = -1; dy <= 1; dy++) {
            const float* gr = gs + (yl+dy)*64;
            const float* tr = ts + (yl+dy)*64;
            #pragma unroll
            for (int dx = -1; dx <= 1; dx++) {
                int xx = x + dx;
                if (xx < 0 || xx > 63) continue;
                float g = gr[xx], v = tr[xx];
                sg += g; st += v; sgg += g*g; sgt += g*v;
            }
        }
        float mg  = sg  * inv9, mt = st * inv9;
        float var = sgg * inv9 - mg*mg;
        float cov = sgt * inv9 - mg*mt;
        float a  = cov / (var + eps);
        float bv = mt - a * mg;
        int oidx = (y0 + (i >> 6))*64 + x;
        g_a [off + oidx] = a;
        g_bv[off + oidx] = bv;
    }
}

// K3b: R=64 -> C=256 projection. px-tile=4 (float4 loads, UNDER TEST),
// o-tile=16, A/B split across blockIdx.z. Per r: 1 LDG.128 + 2 LDS.128 +
// 32 fma2 (half the load overhead of the px2 version). Coalesced float4 out.
// grid: (16 px-blocks, 16 o-blocks, 2 tensors), 256 threads.
__global__ __launch_bounds__(256) void k_proj_rc(const float* __restrict__ wua,
                                                 const float* __restrict__ wub) {
    __shared__ float w_sm[RR*16];
    const float* wt  = (blockIdx.z == 0) ? wua  : wub;   // [o][r] row-major
    const float* src = (blockIdx.z == 0) ? g_a  : g_bv;
    float*       dst = (blockIdx.z == 0) ? g_A  : g_B;
    int o0 = blockIdx.y * 16;
    int t = threadIdx.x;
    for (int i = t; i < RR*16; i += 256) {
        int r = i >> 4, j = i & 15;
        w_sm[i] = wt[(o0 + j)*RR + r];
    }
    __syncthreads();
    int q = (blockIdx.x * 256 + t) * 4;     // 4 consecutive pixels
    int b = q >> 12, rest = q & 4095;
    const float* ps = src + (size_t)b * RR * LRN + rest;
    u64 acc[4][8];
    #pragma unroll
    for (int p = 0; p < 4; p++)
        #pragma unroll
        for (int j = 0; j < 8; j++) acc[p][j] = 0ull;
    #pragma unroll 2
    for (int r = 0; r < RR; r++) {
        float4 v = *(const float4*)(ps + (size_t)r * LRN);
        u64 vv[4];
        vv[0] = pack2(v.x, v.x); vv[1] = pack2(v.y, v.y);
        vv[2] = pack2(v.z, v.z); vv[3] = pack2(v.w, v.w);
        const ulonglong2* wp = (const ulonglong2*)(w_sm + r*16);
        #pragma unroll
        for (int j = 0; j < 4; j++) {
            ulonglong2 w = wp[j];
            #pragma unroll
            for (int p = 0; p < 4; p++) {
                fma2(acc[p][2*j    ], w.x, vv[p]);
                fma2(acc[p][2*j + 1], w.y, vv[p]);
            }
        }
    }
    float* od = dst + (size_t)b * CC * LRN + rest;
    #pragma unroll
    for (int j = 0; j < 8; j++) {
        float2 u0 = unpk(acc[0][j]), u1 = unpk(acc[1][j]);
        float2 u2 = unpk(acc[2][j]), u3 = unpk(acc[3][j]);
        *(float4*)(od + (size_t)(o0 + 2*j    ) * LRN) = make_float4(u0.x, u1.x, u2.x, u3.x);
        *(float4*)(od + (size_t)(o0 + 2*j + 1) * LRN) = make_float4(u0.y, u1.y, u2.y, u3.y);
    }
}

// Per-y bilinear interp of A,B rows from smem (rows local to rbase).
__device__ __forceinline__ void interp_ab(const float* As, const float* Bs,
                                          int y, int rbase, int xg, int cm, int cp,
                                          float4& Av, float4& Bv) {
    float sy = fmaxf((float)y * 0.25f - 0.375f, 0.0f);
    int y0 = (int)sy;
    float wy = sy - (float)y0;
    int y1 = min(y0 + 1, 63);
    const float* rA0 = As + (y0 - rbase)*64; const float* rA1 = As + (y1 - rbase)*64;
    const float* rB0 = Bs + (y0 - rbase)*64; const float* rB1 = Bs + (y1 - rbase)*64;
    float am = rA0[cm] + wy * (rA1[cm] - rA0[cm]);
    float ac = rA0[xg] + wy * (rA1[xg] - rA0[xg]);
    float ap = rA0[cp] + wy * (rA1[cp] - rA0[cp]);
    float bm = rB0[cm] + wy * (rB1[cm] - rB0[cm]);
    float bc = rB0[xg] + wy * (rB1[xg] - rB0[xg]);
    float bp = rB0[cp] + wy * (rB1[cp] - rB0[cp]);
    if (xg == 0) { Av.x = ac; Av.y = ac; Bv.x = bc; Bv.y = bc; }   // src clamp, w=0
    else {
        Av.x = am + 0.625f * (ac - am);
        Av.y = am + 0.875f * (ac - am);
        Bv.x = bm + 0.625f * (bc - bm);
        Bv.y = bm + 0.875f * (bc - bm);
    }
    Av.z = ac + 0.125f * (ap - ac); Av.w = ac + 0.375f * (ap - ac);
    Bv.z = bc + 0.125f * (bp - bc); Bv.w = bc + 0.375f * (bp - bc);
}

// K4: fused bilinear 64->256 upsample of A,B + out = F_dec + A*F_enc + B.
// (Proven R12: ~133us @ 77% DRAM — at its bandwidth ceiling. Control kernel.)
__global__ __launch_bounds__(256) void k_fuse(const float* __restrict__ enc,
                                              const float* __restrict__ dec,
                                              float* __restrict__ out) {
    __shared__ float As[33*64], Bs[33*64];
    int plane = blockIdx.x;
    int half  = blockIdx.y;
    int rbase = half * 31;          // lowres rows rbase..rbase+32 cover this half
    const float* Ap = g_A + (size_t)plane * LRN + rbase*64;
    const float* Bp = g_B + (size_t)plane * LRN + rbase*64;
    int t = threadIdx.x;
    for (int i = t; i < 33*64; i += 256) { As[i] = Ap[i]; Bs[i] = Bp[i]; }
    __syncthreads();
    const float* ep = enc + (size_t)plane * PLN;
    const float* dp = dec + (size_t)plane * PLN;
    float*       op = out + (size_t)plane * PLN;
    int xg = t & 63, ys = t >> 6;
    int cm = max(xg - 1, 0), cp = min(xg + 1, 63);
    int ybase = half*128 + ys;
    #pragma unroll
    for (int yy = 0; yy < 32; yy += 4) {
        int yv[4]; size_t offv[4];
        float4 ev[4], dv[4];
        #pragma unroll
        for (int u = 0; u < 4; u++) {
            yv[u] = ybase + (yy + u)*4;
            offv[u] = (size_t)yv[u] * WW + xg * 4;
        }
        #pragma unroll
        for (int u = 0; u < 4; u++) ev[u] = *(const float4*)(ep + offv[u]);
        #pragma unroll
        for (int u = 0; u < 4; u++) dv[u] = *(const float4*)(dp + offv[u]);
        #pragma unroll
        for (int u = 0; u < 4; u++) {
            float4 Av, Bv;
            interp_ab(As, Bs, yv[u], rbase, xg, cm, cp, Av, Bv);
            float4 o;
            o.x = dv[u].x + Av.x * ev[u].x + Bv.x;
            o.y = dv[u].y + Av.y * ev[u].y + Bv.y;
            o.z = dv[u].z + Av.z * ev[u].z + Bv.z;
            o.w = dv[u].w + Av.w * ev[u].w + Bv.w;
            *(float4*)(op + offv[u]) = o;
        }
    }
}

extern "C" void kernel_launch(void* const* d_in, const int* in_sizes, int n_in,
                              void* d_out, int out_size) {
    const float* F_enc = (const float*)d_in[0];
    const float* F_dec = (const float*)d_in[1];
    const float* w_rg  = (const float*)d_in[2];
    const float* w_rt  = (const float*)d_in[3];
    const float* w_ua  = (const float*)d_in[4];
    const float* w_ub  = (const float*)d_in[5];
    const float* eps   = (const float*)d_in[6];
    float* out = (float*)d_out;

    k_ds_proj<<<dim3(64, 2, 2), 256>>>(F_enc, F_dec, w_rg, w_rt);  // launch 1 (R16 proven)
    k_guided<<<BB*RR*2, 256>>>(eps);                                // launch 2 (proven)
    k_proj_rc<<<dim3(16, 16, 2), 256>>>(w_ua, w_ub);                // launch 3 (px4, under test)
    k_fuse<<<dim3(BB*CC, 2), 256>>>(F_enc, F_dec, out);             // launch 4 -> ncu control
}